// round 6
// baseline (speedup 1.0000x reference)
#include <cuda_runtime.h>
#include <cuda_fp16.h>
#include <cstdint>

#define B_   256
#define P_   196
#define ENC_ 2048
#define DEC_ 512
#define ATT_ 512
#define M_TOT (B_*P_)

// ---------------- scratch (__device__ globals; no cudaMalloc allowed) ------
__device__ float  g_c[B_*ATT_];      // att2 + b_dec + b_enc  (atomic accum)
__device__ float  g_att[M_TOT];      // pre-softmax logits    (atomic accum)
__device__ __half g_Wth[ATT_*ENC_];  // W_enc^T fp16: [n][k] (2 MB)
__device__ __half g_ench[(size_t)M_TOT*ENC_]; // fp16 enc, dumped by k_gemm (205 MB)

// ---------------------------------------------------------------------------
__device__ __forceinline__ uint32_t smem_u32(const void* p) {
    uint32_t a;
    asm("{ .reg .u64 t; cvta.to.shared.u64 t, %1; cvt.u32.u64 %0, t; }" : "=r"(a) : "l"(p));
    return a;
}
__device__ __forceinline__ void cp16(uint32_t dst, const void* src) {
    asm volatile("cp.async.cg.shared.global [%0], [%1], 16;" :: "r"(dst), "l"(src));
}
#define CP_COMMIT() asm volatile("cp.async.commit_group;" ::: "memory")
#define CP_WAIT1()  asm volatile("cp.async.wait_group 1;" ::: "memory")
#define LDSM4(r0,r1,r2,r3,addr) \
    asm volatile("ldmatrix.sync.aligned.m8n8.x4.shared.b16 {%0,%1,%2,%3}, [%4];" \
                 : "=r"(r0),"=r"(r1),"=r"(r2),"=r"(r3) : "r"(addr))

// ---------------------------------------------------------------------------
// Kernel 0: zero atomic accumulators
// ---------------------------------------------------------------------------
__global__ void k_zero() {
    int i = blockIdx.x * 1024 + threadIdx.x;
    if (i < M_TOT)   g_att[i] = 0.f;
    if (i < B_*ATT_) g_c[i]   = 0.f;
}

// ---------------------------------------------------------------------------
// Kernel 0b: transpose+convert W_enc [ENC,ATT] fp32 -> g_Wth [ATT][ENC] fp16
// ---------------------------------------------------------------------------
__global__ void k_transpose(const float* __restrict__ W) {
    __shared__ float t[32][33];
    int k0 = blockIdx.x * 32, n0 = blockIdx.y * 32;
    int x = threadIdx.x, y = threadIdx.y;   // 32 x 8
#pragma unroll
    for (int j = 0; j < 32; j += 8)
        t[y + j][x] = W[(size_t)(k0 + y + j) * ATT_ + n0 + x];
    __syncthreads();
#pragma unroll
    for (int j = 0; j < 32; j += 8)
        g_Wth[(size_t)(n0 + y + j) * ENC_ + k0 + x] = __float2half_rn(t[x][y + j]);
}

// ---------------------------------------------------------------------------
// Kernel 1: split-K att2: g_c[b,a] += dec[b,k0:+128] @ W_dec[k0:+128,a] (+bias)
// ---------------------------------------------------------------------------
__global__ void k_att2(const float* __restrict__ dec,
                       const float* __restrict__ W_dec,
                       const float* __restrict__ b_dec,
                       const float* __restrict__ b_enc) {
    int b0 = blockIdx.x * 4;
    int kz = blockIdx.y;
    int k0 = kz * 128;
    int tid = threadIdx.x;            // 512
    __shared__ float sdec[4][128];
    {
        int bb = tid >> 7, e = tid & 127;
        sdec[bb][e] = dec[(b0 + bb)*DEC_ + k0 + e];
    }
    __syncthreads();
    int a = tid;
    float acc[4] = {0.f, 0.f, 0.f, 0.f};
#pragma unroll 4
    for (int e = 0; e < 128; e++) {
        float w = W_dec[(size_t)(k0 + e)*ATT_ + a];
#pragma unroll
        for (int bb = 0; bb < 4; bb++) acc[bb] += sdec[bb][e] * w;
    }
    float bias = (kz == 0) ? (b_dec[a] + b_enc[a]) : 0.f;
#pragma unroll
    for (int bb = 0; bb < 4; bb++)
        atomicAdd(&g_c[(b0+bb)*ATT_ + a], acc[bb] + bias);
}

// ---------------------------------------------------------------------------
// Kernel 2: fp16 mma.sync fused logits GEMM
//   CTA 128(M) x 256(N), BK=32, 8 warps (2m x 4n), warp tile 64x64,
//   3-stage pipeline, ldmatrix.x4 fragments, in-kernel A fp32->fp16 (+dump).
// ---------------------------------------------------------------------------
#define BM 128
#define BN 256
#define BK 32
#define NK (ENC_/BK)          // 64
#define NSTG 3
#define ROWB 80               // bytes per smem row (32 halves + 8 pad)
#define A_STG (BM*ROWB)       // 10240
#define B_STG (BN*ROWB)       // 20480
#define OFF_A    0
#define OFF_B    (NSTG*A_STG)                   // 30720
#define OFF_CS   (OFF_B + NSTG*B_STG)           // 92160
#define OFF_WS   (OFF_CS + 2*BN*4)              // 94208
#define OFF_SRED (OFF_WS + BN*4)                // 95232
#define SMEM_BYTES (OFF_SRED + BM*4*4)          // 97280

__device__ __forceinline__ void a_ldg(const float* __restrict__ enc, int m0, int kt,
                                      int tid, float4* l) {
    int row = tid >> 1, h = tid & 1;
    const float* src = enc + (size_t)(m0 + row)*ENC_ + kt*BK + h*16;
#pragma unroll
    for (int q = 0; q < 4; q++) l[q] = *(const float4*)(src + q*4);
}
__device__ __forceinline__ void a_sts(char* smem, int stg, int tid, const float4* l,
                                      bool dump, int m0, int kt) {
    int row = tid >> 1, h = tid & 1;
    __half2 hh[8];
#pragma unroll
    for (int q = 0; q < 4; q++) {
        hh[q*2]   = __floats2half2_rn(l[q].x, l[q].y);
        hh[q*2+1] = __floats2half2_rn(l[q].z, l[q].w);
    }
    uint4* d = (uint4*)(smem + OFF_A + stg*A_STG + row*ROWB + h*32);
    d[0] = ((uint4*)hh)[0];
    d[1] = ((uint4*)hh)[1];
    if (dump) {
        uint4* g = (uint4*)(g_ench + (size_t)(m0 + row)*ENC_ + kt*BK + h*16);
        g[0] = ((uint4*)hh)[0];
        g[1] = ((uint4*)hh)[1];
    }
}
__device__ __forceinline__ void b_load(uint32_t smb, int n0, int kt, int stg, int tid) {
    int k0 = kt * BK;
#pragma unroll
    for (int j = 0; j < 4; j++) {
        int i = tid + j*256;
        int row = i >> 2, c = i & 3;
        cp16(smb + OFF_B + stg*B_STG + row*ROWB + c*16,
             g_Wth + (size_t)(n0 + row)*ENC_ + k0 + c*8);
    }
}

__global__ void __launch_bounds__(256, 1)
k_gemm(const float* __restrict__ enc, const float* __restrict__ W_full) {
    extern __shared__ __align__(16) char smem[];
    uint32_t smb = smem_u32(smem);
    float* cs   = (float*)(smem + OFF_CS);    // [2][BN]
    float* ws   = (float*)(smem + OFF_WS);    // [BN]
    float* sred = (float*)(smem + OFF_SRED);  // [BM][4]

    int tid = threadIdx.x;
    int wid = tid >> 5, lane = tid & 31;
    int g = lane >> 2, tg = lane & 3;
    int wm = wid >> 2, wn = wid & 3;          // 2 (m) x 4 (n)
    int n0 = blockIdx.x * BN;
    int m0 = blockIdx.y * BM;
    bool dump = (blockIdx.x == 0);
    int bglob0 = m0 / P_;                     // tile spans <= 2 batches

    // epilogue constants (CTA's n-slice)
    ws[tid] = W_full[n0 + tid];
#pragma unroll
    for (int i = 0; i < 2; i++) {
        int bb = bglob0 + i; if (bb > B_-1) bb = B_-1;
        cs[i*BN + tid] = g_c[bb*ATT_ + n0 + tid];
    }

    float acc[4][8][4];
#pragma unroll
    for (int a = 0; a < 4; a++)
#pragma unroll
        for (int b = 0; b < 8; b++)
#pragma unroll
            for (int c = 0; c < 4; c++) acc[a][b][c] = 0.f;

    // prologue: stages 0,1
#pragma unroll
    for (int s = 0; s < NSTG-1; s++) {
        float4 l[4];
        a_ldg(enc, m0, s, tid, l);
        a_sts(smem, s, tid, l, dump, m0, s);
        b_load(smb, n0, s, s, tid);
        CP_COMMIT();
    }

    // fragment address bases (per-thread constants)
    int arow_off = wm*64 + (lane & 15);
    int a_k16    = ((lane >> 4) & 1) * 16;
    int brow_off = wn*64 + (lane & 7) + ((lane >> 4) << 3);
    int b_k16    = ((lane >> 3) & 1) * 16;

#pragma unroll 1
    for (int kt = 0; kt < NK; kt++) {
        CP_WAIT1();          // B stage kt landed (own view)
        __syncthreads();     // CTA-wide visibility; iter kt-1 fully consumed
        bool pre = (kt + 2 < NK);
        float4 l[4];
        if (pre) {
            a_ldg(enc, m0, kt + 2, tid, l);     // long-latency, STS after MMAs
            b_load(smb, n0, kt + 2, (kt + 2) % NSTG, tid);
        }
        CP_COMMIT();

        int stg = kt % NSTG;
        uint32_t aBase = smb + OFF_A + stg*A_STG + arow_off*ROWB + a_k16;
        uint32_t bBase = smb + OFF_B + stg*B_STG + brow_off*ROWB + b_k16;

        uint32_t af[2][4][4], bf[2][8][2];
#pragma unroll
        for (int kk = 0; kk < 2; kk++)
#pragma unroll
            for (int ms = 0; ms < 4; ms++)
                LDSM4(af[kk][ms][0], af[kk][ms][1], af[kk][ms][2], af[kk][ms][3],
                      aBase + ms*16*ROWB + kk*32);
#pragma unroll
        for (int kk = 0; kk < 2; kk++)
#pragma unroll
            for (int p = 0; p < 4; p++)
                LDSM4(bf[kk][2*p][0], bf[kk][2*p][1], bf[kk][2*p+1][0], bf[kk][2*p+1][1],
                      bBase + p*16*ROWB + kk*32);

#pragma unroll
        for (int kk = 0; kk < 2; kk++)
#pragma unroll
            for (int ms = 0; ms < 4; ms++)
#pragma unroll
                for (int ns = 0; ns < 8; ns++)
                    asm volatile(
                        "mma.sync.aligned.m16n8k16.row.col.f32.f16.f16.f32 "
                        "{%0,%1,%2,%3},{%4,%5,%6,%7},{%8,%9},{%0,%1,%2,%3};"
                        : "+f"(acc[ms][ns][0]), "+f"(acc[ms][ns][1]),
                          "+f"(acc[ms][ns][2]), "+f"(acc[ms][ns][3])
                        : "r"(af[kk][ms][0]), "r"(af[kk][ms][1]),
                          "r"(af[kk][ms][2]), "r"(af[kk][ms][3]),
                          "r"(bf[kk][ns][0]), "r"(bf[kk][ns][1]));

        if (pre) a_sts(smem, (kt + 2) % NSTG, tid, l, dump, m0, kt + 2);
    }

    // fused epilogue: +c, relu, *W_full, reduce over this CTA's 256 cols
#pragma unroll
    for (int ms = 0; ms < 4; ms++) {
#pragma unroll
        for (int h = 0; h < 2; h++) {
            int row = wm*64 + ms*16 + h*8 + g;
            int m = m0 + row;
            int bsel = (m / P_) - bglob0;
            const float* csr = cs + bsel*BN;
            float s = 0.f;
#pragma unroll
            for (int ns = 0; ns < 8; ns++) {
#pragma unroll
                for (int j = 0; j < 2; j++) {
                    int col = wn*64 + ns*8 + tg*2 + j;
                    float v = acc[ms][ns][h*2 + j] + csr[col];
                    s += fmaxf(v, 0.f) * ws[col];
                }
            }
            s += __shfl_xor_sync(0xffffffffu, s, 1);
            s += __shfl_xor_sync(0xffffffffu, s, 2);
            if (tg == 0) sred[row*4 + wn] = s;
        }
    }
    __syncthreads();
    if (tid < BM) {
        float s = 0.f;
#pragma unroll
        for (int w = 0; w < 4; w++) s += sred[tid*4 + w];
        atomicAdd(&g_att[m0 + tid], s);
    }
}

// ---------------------------------------------------------------------------
// Kernel 3: fused softmax (over P) + context GEMV from fp16 enc dump
// ---------------------------------------------------------------------------
__global__ void k_softctx(float* __restrict__ alpha, float* __restrict__ ctx) {
    int b = blockIdx.x, t = threadIdx.x;
    __shared__ float sm[256];
    __shared__ float sal[P_];
    float x = (t < P_) ? g_att[b*P_ + t] : -1e30f;
    sm[t] = x; __syncthreads();
#pragma unroll
    for (int s = 128; s > 0; s >>= 1) {
        if (t < s) sm[t] = fmaxf(sm[t], sm[t+s]);
        __syncthreads();
    }
    float mx = sm[0]; __syncthreads();
    float e = (t < P_) ? __expf(x - mx) : 0.f;
    sm[t] = e; __syncthreads();
#pragma unroll
    for (int s = 128; s > 0; s >>= 1) {
        if (t < s) sm[t] += sm[t+s];
        __syncthreads();
    }
    float inv = 1.f / sm[0];
    float av = e * inv;
    if (t < P_) {
        sal[t] = av;
        alpha[b*P_ + t] = av;
    }
    __syncthreads();

    int e0 = t * 8;   // 256 threads x 8 halves = 2048 = ENC_
    const __half* base = g_ench + (size_t)b * P_ * ENC_ + e0;
    float acc[8] = {0.f,0.f,0.f,0.f,0.f,0.f,0.f,0.f};
#pragma unroll 2
    for (int p = 0; p < P_; p++) {
        float a = sal[p];
        uint4 raw = *(const uint4*)(base + (size_t)p * ENC_);
        const __half2* h = (const __half2*)&raw;
#pragma unroll
        for (int q = 0; q < 4; q++) {
            float2 f = __half22float2(h[q]);
            acc[q*2]   += a * f.x;
            acc[q*2+1] += a * f.y;
        }
    }
    float4* o = (float4*)(ctx + (size_t)b*ENC_ + e0);
    o[0] = make_float4(acc[0], acc[1], acc[2], acc[3]);
    o[1] = make_float4(acc[4], acc[5], acc[6], acc[7]);
}

// ---------------------------------------------------------------------------
extern "C" void kernel_launch(void* const* d_in, const int* in_sizes, int n_in,
                              void* d_out, int out_size) {
    const float* enc    = (const float*)d_in[0];
    const float* dec    = (const float*)d_in[1];
    const float* W_enc  = (const float*)d_in[2];
    const float* b_enc  = (const float*)d_in[3];
    const float* W_dec  = (const float*)d_in[4];
    const float* b_dec  = (const float*)d_in[5];
    const float* W_full = (const float*)d_in[6];
    (void)in_sizes; (void)n_in; (void)out_size;

    float* out   = (float*)d_out;
    float* ctx   = out;               // [B, ENC]
    float* alpha = out + B_*ENC_;     // [B, P]

    static int smem_set = 0;
    if (!smem_set) {
        cudaFuncSetAttribute(k_gemm, cudaFuncAttributeMaxDynamicSharedMemorySize, SMEM_BYTES);
        smem_set = 1;
    }

    k_zero     <<<(B_*ATT_ + 1023)/1024, 1024>>>();
    k_transpose<<<dim3(ENC_/32, ATT_/32), dim3(32, 8)>>>(W_enc);
    k_att2     <<<dim3(B_/4, 4), 512>>>(dec, W_dec, b_dec, b_enc);
    k_gemm     <<<dim3(ATT_/BN, M_TOT/BM), 256, SMEM_BYTES>>>(enc, W_full);
    k_softctx  <<<B_, 256>>>(alpha, ctx);
}